// round 2
// baseline (speedup 1.0000x reference)
#include <cuda_runtime.h>

#define NN 5000   // nodes per level
#define BB 1024   // batch
#define KK 16     // fan-in
#define NLEV 9    // L-1 level applications
#define NEG_SLOPE 0.1f

// Ping-pong activation buffers in [N, B] (node-major) layout: 2 x 20.48 MB.
__device__ float g_act[2][NN * BB];

// ---------------------------------------------------------------------------
// Transpose input x [B, N] -> g_act[0] [N, B]
// ---------------------------------------------------------------------------
__global__ void tin_kernel(const float* __restrict__ x) {
    __shared__ float tile[32][33];
    int n = blockIdx.x * 32 + threadIdx.x;
    int b = blockIdx.y * 32 + threadIdx.y;     // B = 1024 divisible by 32
    if (n < NN) tile[threadIdx.y][threadIdx.x] = x[b * NN + n];
    __syncthreads();
    int b2 = blockIdx.y * 32 + threadIdx.x;
    int n2 = blockIdx.x * 32 + threadIdx.y;
    if (n2 < NN) g_act[0][n2 * BB + b2] = tile[threadIdx.x][threadIdx.y];
}

// ---------------------------------------------------------------------------
// One level: for node n, out[n][:] = leaky(sum_k w[n][k] * act[s[n][k]][:] + bias[n])
// One block per node; 256 threads x float4 = 1024 batch lanes.
// ---------------------------------------------------------------------------
__global__ __launch_bounds__(256) void level_kernel(int ssel,
                                                    const int* __restrict__ sidx,
                                                    const float* __restrict__ w,
                                                    const float* __restrict__ bias) {
    const float* __restrict__ src = g_act[ssel];
    float* __restrict__ dst = g_act[ssel ^ 1];

    int n = blockIdx.x;
    int t = threadIdx.x;

    __shared__ int   s_idx[KK];
    __shared__ float s_w[KK];
    if (t < KK) {
        s_idx[t] = sidx[n * KK + t];
        s_w[t]   = w[n * KK + t];
    }
    __syncthreads();

    float bv = bias[n];
    float4 acc = make_float4(bv, bv, bv, bv);

#pragma unroll
    for (int k = 0; k < KK; k++) {
        const float4* row = reinterpret_cast<const float4*>(src + s_idx[k] * BB);
        float4 v = __ldg(&row[t]);
        float wk = s_w[k];
        acc.x = fmaf(v.x, wk, acc.x);
        acc.y = fmaf(v.y, wk, acc.y);
        acc.z = fmaf(v.z, wk, acc.z);
        acc.w = fmaf(v.w, wk, acc.w);
    }

    acc.x = acc.x > 0.0f ? acc.x : NEG_SLOPE * acc.x;
    acc.y = acc.y > 0.0f ? acc.y : NEG_SLOPE * acc.y;
    acc.z = acc.z > 0.0f ? acc.z : NEG_SLOPE * acc.z;
    acc.w = acc.w > 0.0f ? acc.w : NEG_SLOPE * acc.w;

    reinterpret_cast<float4*>(dst + n * BB)[t] = acc;
}

// ---------------------------------------------------------------------------
// Transpose final activations g_act[sel] [N, B] -> out [B, N]
// ---------------------------------------------------------------------------
__global__ void tout_kernel(int sel, float* __restrict__ out) {
    __shared__ float tile[32][33];
    int b = blockIdx.x * 32 + threadIdx.x;
    int n = blockIdx.y * 32 + threadIdx.y;
    if (n < NN) tile[threadIdx.y][threadIdx.x] = g_act[sel][n * BB + b];
    __syncthreads();
    int n2 = blockIdx.y * 32 + threadIdx.x;
    int b2 = blockIdx.x * 32 + threadIdx.y;
    if (n2 < NN) out[b2 * NN + n2] = tile[threadIdx.x][threadIdx.y];
}

// ---------------------------------------------------------------------------
extern "C" void kernel_launch(void* const* d_in, const int* in_sizes, int n_in,
                              void* d_out, int out_size) {
    const float* x     = (const float*)d_in[0];   // [B, N] fp32
    const int*   sidx  = (const int*)d_in[1];     // [NLEV, N, K] int32
    const float* w     = (const float*)d_in[2];   // [NLEV, N, K] fp32
    const float* bias  = (const float*)d_in[3];   // [NLEV, N]    fp32
    float* out = (float*)d_out;                   // [B, N] fp32

    dim3 tblk(32, 32);
    dim3 tin_grid((NN + 31) / 32, BB / 32);
    tin_kernel<<<tin_grid, tblk>>>(x);

    for (int l = 0; l < NLEV; l++) {
        level_kernel<<<NN, 256>>>(l & 1,
                                  sidx + (size_t)l * NN * KK,
                                  w    + (size_t)l * NN * KK,
                                  bias + (size_t)l * NN);
    }

    // NLEV=9 levels starting from buf 0: final result lives in buf (NLEV & 1) = 1
    dim3 tout_grid(BB / 32, (NN + 31) / 32);
    tout_kernel<<<tout_grid, tblk>>>(NLEV & 1, out);
}